// round 12
// baseline (speedup 1.0000x reference)
#include <cuda_runtime.h>
#include <cstdint>

// Problem constants (fixed by the dataset)
#define C_DIM 22
#define T_DIM 4000
#define M_DIM 16
#define B_DIM 16

// Tiling
#define TT        512       // t-tile per ring slot
#define TPI       8         // tiles per item = ceil(4000/512)
#define DEPTH     4         // ring slots
#define BLOCK     256
#define GRID_P    128       // 128 CTAs x 8 items = 1024 items, perfectly balanced

typedef unsigned long long u64;

// packed dual-fp32 FMA: d = a*b + c (elementwise on {lo,hi})
__device__ __forceinline__ u64 fma2(u64 a, u64 b, u64 c) {
    u64 d;
    asm("fma.rn.f32x2 %0, %1, %2, %3;" : "=l"(d) : "l"(a), "l"(b), "l"(c));
    return d;
}
__device__ __forceinline__ u64 dup2(float v) {
    u64 d; asm("mov.b64 %0, {%1, %1};" : "=l"(d) : "f"(v)); return d;
}

// Stage flat tile jj (item i0 + jj/8, tile jj%8) into ring slot jj&3.
// 22 rows x 512 floats. 256 threads: thread covers rows (tid>>7), (tid>>7)+2, ...
// 16B per row per thread; zero-fills the t>=4000 tail (no DRAM traffic for it).
__device__ __forceinline__ void stage_tile(float* bufs, const float* __restrict__ xfb,
                                           int i0, int jj, int tid)
{
    float* dst = bufs + (jj & (DEPTH - 1)) * (C_DIM * TT);
    const float* gx = xfb + (size_t)(i0 + (jj >> 3)) * (C_DIM * T_DIM);
    const int tg   = (jj & (TPI - 1)) * TT + ((tid & 127) << 2); // global t
    const unsigned ss = (tg < T_DIM) ? 16u : 0u;                 // zero-fill OOB
    const float* src  = ss ? (gx + tg) : gx;                     // clamp OOB addr
    const int c0   = tid >> 7;                                   // 0 or 1
    const int soff = ((tid & 127) << 2);
    #pragma unroll
    for (int c = c0; c < C_DIM; c += 2) {
        unsigned sa = (unsigned)__cvta_generic_to_shared(dst + c * TT + soff);
        asm volatile("cp.async.cg.shared.global [%0], [%1], 16, %2;"
                     :: "r"(sa), "l"(src + c * T_DIM), "r"(ss));
    }
}

// Each CTA processes `per` contiguous items. Flat tile stream with a 4-deep
// cp.async ring (prefetch distance 3) keeps ~135KB of DRAM reads in flight.
// out[item,m] = log(diag[m]/sum(diag)); diag[m] = sum_t (sum_c W[b,m,c]*x[c,t])^2.
// (The reference's 1/sqrt(T) scaling cancels in the ratio and is skipped.)
__global__ void __launch_bounds__(BLOCK, 1)
csp_kernel(const float* __restrict__ xfb, const float* __restrict__ WT,
           float* __restrict__ out, int n_items, int per)
{
    extern __shared__ float sm[];
    float* bufs = sm;                              // DEPTH * 22 * 512 floats
    float* red  = sm + DEPTH * C_DIM * TT;         // 32 floats scratch

    const int tid  = threadIdx.x;
    const int lane = tid & 31;
    const int wid  = tid >> 5;
    const int g    = wid & 3;                      // m-group: m in [4g, 4g+4)
    const int h    = wid >> 2;                     // t-half within a tile

    const int i0 = blockIdx.x * per;
    int i1 = i0 + per; if (i1 > n_items) i1 = n_items;
    if (i0 >= i1) return;
    const int ntile = (i1 - i0) * TPI;

    // Prologue: fill 3 ring slots.
    stage_tile(bufs, xfb, i0, 0, tid);
    asm volatile("cp.async.commit_group;");
    stage_tile(bufs, xfb, i0, 1, tid);
    asm volatile("cp.async.commit_group;");
    stage_tile(bufs, xfb, i0, 2, tid);
    asm volatile("cp.async.commit_group;");

    u64 w0[C_DIM], w1[C_DIM], w2[C_DIM], w3[C_DIM];
    u64 acc0 = 0ull, acc1 = 0ull, acc2 = 0ull, acc3 = 0ull;
    const int tlb = (h << 8) + (lane << 1);        // base t within a tile

    for (int j = 0; j < ntile; j++) {
        // Tile j complete when <=2 younger groups remain (one group/iteration).
        asm volatile("cp.async.wait_group 2;");
        __syncthreads();   // (a) tile j visible to all  (b) tile j-1 fully consumed

        // Stage tile j+3 into slot (j+3)&3 == (j-1)&3, consumed at iter j-1,
        // which every thread finished before this barrier.
        if (j + 3 < ntile)
            stage_tile(bufs, xfb, i0, j + 3, tid);
        asm volatile("cp.async.commit_group;");     // always: keeps group count in sync

        if ((j & (TPI - 1)) == 0) {
            // New item: load this warp's 4 W rows (L1/L2-resident), reset accs.
            const int item = i0 + (j >> 3);
            const float* wg = WT + (size_t)((item & (B_DIM - 1)) * M_DIM + g * 4) * C_DIM;
            #pragma unroll
            for (int c = 0; c < C_DIM; c++) {
                w0[c] = dup2(__ldg(wg + c));
                w1[c] = dup2(__ldg(wg + C_DIM + c));
                w2[c] = dup2(__ldg(wg + 2 * C_DIM + c));
                w3[c] = dup2(__ldg(wg + 3 * C_DIM + c));
            }
            acc0 = acc1 = acc2 = acc3 = 0ull;
        }

        const float* xs = bufs + (j & (DEPTH - 1)) * (C_DIM * TT);

        #pragma unroll
        for (int it = 0; it < 4; it++) {
            const float* xp = xs + tlb + (it << 6);
            u64 z0 = 0ull, z1 = 0ull, z2 = 0ull, z3 = 0ull;
            #pragma unroll
            for (int c = 0; c < C_DIM; c++) {
                u64 xd = *(const u64*)(xp + c * TT);   // float2 of {t, t+1}
                z0 = fma2(w0[c], xd, z0);
                z1 = fma2(w1[c], xd, z1);
                z2 = fma2(w2[c], xd, z2);
                z3 = fma2(w3[c], xd, z3);
            }
            acc0 = fma2(z0, z0, acc0);
            acc1 = fma2(z1, z1, acc1);
            acc2 = fma2(z2, z2, acc2);
            acc3 = fma2(z3, z3, acc3);
        }

        if ((j & (TPI - 1)) == TPI - 1) {
            // ---- end of item: reduce diag[m], log-normalize, write out ----
            const int item = i0 + (j >> 3);
            float a0, a1, a2, a3;
            {
                float lo, hi;
                asm("mov.b64 {%0, %1}, %2;" : "=f"(lo), "=f"(hi) : "l"(acc0)); a0 = lo + hi;
                asm("mov.b64 {%0, %1}, %2;" : "=f"(lo), "=f"(hi) : "l"(acc1)); a1 = lo + hi;
                asm("mov.b64 {%0, %1}, %2;" : "=f"(lo), "=f"(hi) : "l"(acc2)); a2 = lo + hi;
                asm("mov.b64 {%0, %1}, %2;" : "=f"(lo), "=f"(hi) : "l"(acc3)); a3 = lo + hi;
            }
            #pragma unroll
            for (int off = 16; off; off >>= 1) {
                a0 += __shfl_xor_sync(0xffffffffu, a0, off);
                a1 += __shfl_xor_sync(0xffffffffu, a1, off);
                a2 += __shfl_xor_sync(0xffffffffu, a2, off);
                a3 += __shfl_xor_sync(0xffffffffu, a3, off);
            }
            if (lane == 0) {
                red[(h << 4) + g * 4 + 0] = a0;
                red[(h << 4) + g * 4 + 1] = a1;
                red[(h << 4) + g * 4 + 2] = a2;
                red[(h << 4) + g * 4 + 3] = a3;
            }
            __syncthreads();
            if (tid < M_DIM) red[tid] = red[tid] + red[M_DIM + tid];
            __syncthreads();
            if (tid < M_DIM) {
                float tot = 0.f;
                #pragma unroll
                for (int jj = 0; jj < M_DIM; jj++) tot += red[jj];
                out[item * M_DIM + tid] = logf(red[tid] / tot);
            }
            // red[] is next touched TPI tiles later, behind multiple barriers.
        }
    }
}

extern "C" void kernel_launch(void* const* d_in, const int* in_sizes, int n_in,
                              void* d_out, int out_size) {
    const float* xfb = (const float*)d_in[0];
    const float* WT  = (const float*)d_in[1];
    int nx = in_sizes[0];
    // Defensive: ensure xfb is the big tensor
    if (n_in >= 2 && in_sizes[0] < in_sizes[1]) {
        xfb = (const float*)d_in[1];
        WT  = (const float*)d_in[0];
        nx  = in_sizes[1];
    }
    const int n_items = nx / (C_DIM * T_DIM);     // = 1024 (N*B)

    int grid = GRID_P; if (grid > n_items) grid = n_items;
    const int per = (n_items + grid - 1) / grid;  // 8 items per CTA

    const size_t smem_bytes =
        (size_t)(DEPTH * C_DIM * TT + 64) * sizeof(float);

    cudaFuncSetAttribute((const void*)csp_kernel,
                         cudaFuncAttributeMaxDynamicSharedMemorySize,
                         (int)smem_bytes);

    csp_kernel<<<grid, BLOCK, smem_bytes>>>(xfb, WT, (float*)d_out, n_items, per);
}

// round 13
// speedup vs baseline: 1.0004x; 1.0004x over previous
#include <cuda_runtime.h>
#include <cstdint>

// Problem constants (fixed by the dataset)
#define C_DIM 22
#define T_DIM 4000
#define M_DIM 16
#define B_DIM 16

// Tiling
#define TT        512       // t-tile per ring slot
#define TPI       8         // tiles per item = ceil(4000/512)
#define DEPTH     4         // ring slots
#define BLOCK     256
#define GRID_P    128       // 128 CTAs x 8 items = 1024 items, perfectly balanced

typedef unsigned long long u64;

// packed dual-fp32 FMA: d = a*b + c (elementwise on {lo,hi})
__device__ __forceinline__ u64 fma2(u64 a, u64 b, u64 c) {
    u64 d;
    asm("fma.rn.f32x2 %0, %1, %2, %3;" : "=l"(d) : "l"(a), "l"(b), "l"(c));
    return d;
}
__device__ __forceinline__ u64 dup2(float v) {
    u64 d; asm("mov.b64 %0, {%1, %1};" : "=l"(d) : "f"(v)); return d;
}

// Stage flat tile jj (item i0 + jj/8, tile jj%8) into ring slot jj&3.
// 22 rows x 512 floats. 256 threads: thread covers rows (tid>>7), (tid>>7)+2, ...
// 16B per row per thread; zero-fills the t>=4000 tail (no DRAM traffic for it).
__device__ __forceinline__ void stage_tile(float* bufs, const float* __restrict__ xfb,
                                           int i0, int jj, int tid)
{
    float* dst = bufs + (jj & (DEPTH - 1)) * (C_DIM * TT);
    const float* gx = xfb + (size_t)(i0 + (jj >> 3)) * (C_DIM * T_DIM);
    const int tg   = (jj & (TPI - 1)) * TT + ((tid & 127) << 2); // global t
    const unsigned ss = (tg < T_DIM) ? 16u : 0u;                 // zero-fill OOB
    const float* src  = ss ? (gx + tg) : gx;                     // clamp OOB addr
    const int c0   = tid >> 7;                                   // 0 or 1
    const int soff = ((tid & 127) << 2);
    #pragma unroll
    for (int c = c0; c < C_DIM; c += 2) {
        unsigned sa = (unsigned)__cvta_generic_to_shared(dst + c * TT + soff);
        asm volatile("cp.async.cg.shared.global [%0], [%1], 16, %2;"
                     :: "r"(sa), "l"(src + c * T_DIM), "r"(ss));
    }
}

// Each CTA processes `per` contiguous items. Flat tile stream with a 4-deep
// cp.async ring (prefetch distance 3) keeps ~135KB of DRAM reads in flight.
// out[item,m] = log(diag[m]/sum(diag)); diag[m] = sum_t (sum_c W[b,m,c]*x[c,t])^2.
// (The reference's 1/sqrt(T) scaling cancels in the ratio and is skipped.)
__global__ void __launch_bounds__(BLOCK, 1)
csp_kernel(const float* __restrict__ xfb, const float* __restrict__ WT,
           float* __restrict__ out, int n_items, int per)
{
    extern __shared__ float sm[];
    float* bufs = sm;                              // DEPTH * 22 * 512 floats
    float* red  = sm + DEPTH * C_DIM * TT;         // 32 floats scratch

    const int tid  = threadIdx.x;
    const int lane = tid & 31;
    const int wid  = tid >> 5;
    const int g    = wid & 3;                      // m-group: m in [4g, 4g+4)
    const int h    = wid >> 2;                     // t-half within a tile

    const int i0 = blockIdx.x * per;
    int i1 = i0 + per; if (i1 > n_items) i1 = n_items;
    if (i0 >= i1) return;
    const int ntile = (i1 - i0) * TPI;

    // Prologue: fill 3 ring slots.
    stage_tile(bufs, xfb, i0, 0, tid);
    asm volatile("cp.async.commit_group;");
    stage_tile(bufs, xfb, i0, 1, tid);
    asm volatile("cp.async.commit_group;");
    stage_tile(bufs, xfb, i0, 2, tid);
    asm volatile("cp.async.commit_group;");

    u64 w0[C_DIM], w1[C_DIM], w2[C_DIM], w3[C_DIM];
    u64 acc0 = 0ull, acc1 = 0ull, acc2 = 0ull, acc3 = 0ull;
    const int tlb = (h << 8) + (lane << 1);        // base t within a tile

    for (int j = 0; j < ntile; j++) {
        // Tile j complete when <=2 younger groups remain (one group/iteration).
        asm volatile("cp.async.wait_group 2;");
        __syncthreads();   // (a) tile j visible to all  (b) tile j-1 fully consumed

        // Stage tile j+3 into slot (j+3)&3 == (j-1)&3, consumed at iter j-1,
        // which every thread finished before this barrier.
        if (j + 3 < ntile)
            stage_tile(bufs, xfb, i0, j + 3, tid);
        asm volatile("cp.async.commit_group;");     // always: keeps group count in sync

        if ((j & (TPI - 1)) == 0) {
            // New item: load this warp's 4 W rows (L1/L2-resident), reset accs.
            const int item = i0 + (j >> 3);
            const float* wg = WT + (size_t)((item & (B_DIM - 1)) * M_DIM + g * 4) * C_DIM;
            #pragma unroll
            for (int c = 0; c < C_DIM; c++) {
                w0[c] = dup2(__ldg(wg + c));
                w1[c] = dup2(__ldg(wg + C_DIM + c));
                w2[c] = dup2(__ldg(wg + 2 * C_DIM + c));
                w3[c] = dup2(__ldg(wg + 3 * C_DIM + c));
            }
            acc0 = acc1 = acc2 = acc3 = 0ull;
        }

        const float* xs = bufs + (j & (DEPTH - 1)) * (C_DIM * TT);

        #pragma unroll
        for (int it = 0; it < 4; it++) {
            const float* xp = xs + tlb + (it << 6);
            u64 z0 = 0ull, z1 = 0ull, z2 = 0ull, z3 = 0ull;
            #pragma unroll
            for (int c = 0; c < C_DIM; c++) {
                u64 xd = *(const u64*)(xp + c * TT);   // float2 of {t, t+1}
                z0 = fma2(w0[c], xd, z0);
                z1 = fma2(w1[c], xd, z1);
                z2 = fma2(w2[c], xd, z2);
                z3 = fma2(w3[c], xd, z3);
            }
            acc0 = fma2(z0, z0, acc0);
            acc1 = fma2(z1, z1, acc1);
            acc2 = fma2(z2, z2, acc2);
            acc3 = fma2(z3, z3, acc3);
        }

        if ((j & (TPI - 1)) == TPI - 1) {
            // ---- end of item: reduce diag[m], log-normalize, write out ----
            const int item = i0 + (j >> 3);
            float a0, a1, a2, a3;
            {
                float lo, hi;
                asm("mov.b64 {%0, %1}, %2;" : "=f"(lo), "=f"(hi) : "l"(acc0)); a0 = lo + hi;
                asm("mov.b64 {%0, %1}, %2;" : "=f"(lo), "=f"(hi) : "l"(acc1)); a1 = lo + hi;
                asm("mov.b64 {%0, %1}, %2;" : "=f"(lo), "=f"(hi) : "l"(acc2)); a2 = lo + hi;
                asm("mov.b64 {%0, %1}, %2;" : "=f"(lo), "=f"(hi) : "l"(acc3)); a3 = lo + hi;
            }
            #pragma unroll
            for (int off = 16; off; off >>= 1) {
                a0 += __shfl_xor_sync(0xffffffffu, a0, off);
                a1 += __shfl_xor_sync(0xffffffffu, a1, off);
                a2 += __shfl_xor_sync(0xffffffffu, a2, off);
                a3 += __shfl_xor_sync(0xffffffffu, a3, off);
            }
            if (lane == 0) {
                red[(h << 4) + g * 4 + 0] = a0;
                red[(h << 4) + g * 4 + 1] = a1;
                red[(h << 4) + g * 4 + 2] = a2;
                red[(h << 4) + g * 4 + 3] = a3;
            }
            __syncthreads();
            if (tid < M_DIM) red[tid] = red[tid] + red[M_DIM + tid];
            __syncthreads();
            if (tid < M_DIM) {
                float tot = 0.f;
                #pragma unroll
                for (int jj = 0; jj < M_DIM; jj++) tot += red[jj];
                out[item * M_DIM + tid] = logf(red[tid] / tot);
            }
            // red[] is next touched TPI tiles later, behind multiple barriers.
        }
    }
}

extern "C" void kernel_launch(void* const* d_in, const int* in_sizes, int n_in,
                              void* d_out, int out_size) {
    const float* xfb = (const float*)d_in[0];
    const float* WT  = (const float*)d_in[1];
    int nx = in_sizes[0];
    // Defensive: ensure xfb is the big tensor
    if (n_in >= 2 && in_sizes[0] < in_sizes[1]) {
        xfb = (const float*)d_in[1];
        WT  = (const float*)d_in[0];
        nx  = in_sizes[1];
    }
    const int n_items = nx / (C_DIM * T_DIM);     // = 1024 (N*B)

    int grid = GRID_P; if (grid > n_items) grid = n_items;
    const int per = (n_items + grid - 1) / grid;  // 8 items per CTA

    const size_t smem_bytes =
        (size_t)(DEPTH * C_DIM * TT + 64) * sizeof(float);

    cudaFuncSetAttribute((const void*)csp_kernel,
                         cudaFuncAttributeMaxDynamicSharedMemorySize,
                         (int)smem_bytes);

    csp_kernel<<<grid, BLOCK, smem_bytes>>>(xfb, WT, (float*)d_out, n_items, per);
}

// round 14
// speedup vs baseline: 1.1019x; 1.1015x over previous
#include <cuda_runtime.h>
#include <cstdint>

// Problem constants (fixed by the dataset)
#define C_DIM 22
#define T_DIM 4000
#define M_DIM 16
#define B_DIM 16

// Tiling: 512-t double-buffered tiles, 8 tiles per item, 2 CTAs per SM.
#define TT    512
#define TPI   8          // ceil(4000/512), tail zero-filled
#define BLOCK 256

typedef unsigned long long u64;

// packed dual-fp32 FMA: d = a*b + c (elementwise on {lo,hi})
__device__ __forceinline__ u64 fma2(u64 a, u64 b, u64 c) {
    u64 d;
    asm("fma.rn.f32x2 %0, %1, %2, %3;" : "=l"(d) : "l"(a), "l"(b), "l"(c));
    return d;
}
__device__ __forceinline__ u64 dup2(float v) {
    u64 d; asm("mov.b64 %0, {%1, %1};" : "=l"(d) : "f"(v)); return d;
}

// Stage tile k of this item: 22 rows x 512 floats (45KB), 11 cp.async per thread.
// Zero-fills the t>=4000 tail (tile 7) without DRAM traffic.
__device__ __forceinline__ void stage_tile(float* dst, const float* __restrict__ gx,
                                           int k, int tid)
{
    const int tg = k * TT + ((tid & 127) << 2);      // global t of this 16B chunk
    const unsigned ss = (tg < T_DIM) ? 16u : 0u;     // src-size 0 => zero-fill
    const float* src = ss ? (gx + tg) : gx;          // clamp OOB address
    const int c0   = tid >> 7;                       // 0 or 1
    const int soff = (tid & 127) << 2;
    #pragma unroll
    for (int c = c0; c < C_DIM; c += 2) {
        unsigned sa = (unsigned)__cvta_generic_to_shared(dst + c * TT + soff);
        asm volatile("cp.async.cg.shared.global [%0], [%1], 16, %2;"
                     :: "r"(sa), "l"(src + c * T_DIM), "r"(ss));
    }
}

// One CTA per item (n*16+b). out[item,m] = log(diag[m]/sum_m diag[m]),
// diag[m] = sum_t (sum_c W[b,m,c]*x[c,t])^2. The reference's 1/sqrt(T)
// scaling cancels in the ratio and is skipped.
// W lives in smem as pre-duplicated f32x2 pairs so no W registers are held
// across the mainloop -> fits 2 CTAs/SM (independent barrier domains: one
// CTA computes while the other waits on DRAM).
__global__ void __launch_bounds__(BLOCK, 2)
csp_kernel(const float* __restrict__ xfb, const float* __restrict__ WT,
           float* __restrict__ out)
{
    extern __shared__ float sm[];
    float* xb  = sm;                                  // 2 * 22*512 floats
    u64*   w2  = (u64*)(sm + 2 * C_DIM * TT);         // 22*16 dup'd pairs (16B-aligned)
    float* red = (float*)(w2 + C_DIM * M_DIM);        // 32 floats scratch

    const int tid  = threadIdx.x;
    const int lane = tid & 31;
    const int wid  = tid >> 5;
    const int g    = wid & 3;                         // m-group: m in [4g, 4g+4)
    const int h    = wid >> 2;                        // t-half within a tile

    const int item = blockIdx.x;
    const float* gx = xfb + (size_t)item * (C_DIM * T_DIM);

    // Kick off DRAM immediately.
    stage_tile(xb, gx, 0, tid);
    asm volatile("cp.async.commit_group;");

    // Fill w2[c*16+m] = dup{W[b,m,c]} while tile 0 is in flight.
    {
        const float* wb = WT + (size_t)(item & (B_DIM - 1)) * (M_DIM * C_DIM);
        #pragma unroll
        for (int idx = tid; idx < C_DIM * M_DIM; idx += BLOCK) {
            const int m = idx & 15, c = idx >> 4;
            w2[idx] = dup2(__ldg(wb + m * C_DIM + c));
        }
    }

    u64 acc[4] = {0ull, 0ull, 0ull, 0ull};            // sum z^2, packed over t-pairs
    const int tlb = (h << 8) + (lane << 1);           // this thread's base t in a tile
    const u64* wp = w2 + 4 * g;                       // this warp's 4 m's

    #pragma unroll 1
    for (int k = 0; k < TPI; k++) {
        // Prefetch tile k+1 into the other slot (last read two barriers ago),
        // then wait for tile k. At k=7 drain everything.
        if (k + 1 < TPI) {
            stage_tile(xb + ((k + 1) & 1) * (C_DIM * TT), gx, k + 1, tid);
            asm volatile("cp.async.commit_group;");
            asm volatile("cp.async.wait_group 1;");
        } else {
            asm volatile("cp.async.wait_group 0;");
        }
        __syncthreads();   // tile k (and w2 at k=0) visible to all warps

        const float* xs = xb + (k & 1) * (C_DIM * TT) + tlb;

        u64 z[4][4];       // [m][t-pair], 16 independent FMA chains
        #pragma unroll
        for (int j = 0; j < 4; j++)
            z[j][0] = z[j][1] = z[j][2] = z[j][3] = 0ull;

        #pragma unroll
        for (int c = 0; c < C_DIM; c++) {
            const ulonglong2 p0 = *(const ulonglong2*)(wp + c * 16);      // m 4g,4g+1
            const ulonglong2 p1 = *(const ulonglong2*)(wp + c * 16 + 2);  // m 4g+2,4g+3
            #pragma unroll
            for (int tp = 0; tp < 4; tp++) {
                const u64 xd = *(const u64*)(xs + c * TT + tp * 64); // {t, t+1}
                z[0][tp] = fma2(p0.x, xd, z[0][tp]);
                z[1][tp] = fma2(p0.y, xd, z[1][tp]);
                z[2][tp] = fma2(p1.x, xd, z[2][tp]);
                z[3][tp] = fma2(p1.y, xd, z[3][tp]);
            }
        }
        #pragma unroll
        for (int j = 0; j < 4; j++) {
            acc[j] = fma2(z[j][0], z[j][0], acc[j]);
            acc[j] = fma2(z[j][1], z[j][1], acc[j]);
            acc[j] = fma2(z[j][2], z[j][2], acc[j]);
            acc[j] = fma2(z[j][3], z[j][3], acc[j]);
        }
        __syncthreads();   // all reads of this slot done before it is re-staged
    }

    // ---- reduction: diag[m] over lanes, then over the two t-half warps ----
    float a0, a1, a2, a3;
    {
        float lo, hi;
        asm("mov.b64 {%0, %1}, %2;" : "=f"(lo), "=f"(hi) : "l"(acc[0])); a0 = lo + hi;
        asm("mov.b64 {%0, %1}, %2;" : "=f"(lo), "=f"(hi) : "l"(acc[1])); a1 = lo + hi;
        asm("mov.b64 {%0, %1}, %2;" : "=f"(lo), "=f"(hi) : "l"(acc[2])); a2 = lo + hi;
        asm("mov.b64 {%0, %1}, %2;" : "=f"(lo), "=f"(hi) : "l"(acc[3])); a3 = lo + hi;
    }
    #pragma unroll
    for (int off = 16; off; off >>= 1) {
        a0 += __shfl_xor_sync(0xffffffffu, a0, off);
        a1 += __shfl_xor_sync(0xffffffffu, a1, off);
        a2 += __shfl_xor_sync(0xffffffffu, a2, off);
        a3 += __shfl_xor_sync(0xffffffffu, a3, off);
    }
    if (lane == 0) {
        red[(h << 4) + g * 4 + 0] = a0;
        red[(h << 4) + g * 4 + 1] = a1;
        red[(h << 4) + g * 4 + 2] = a2;
        red[(h << 4) + g * 4 + 3] = a3;
    }
    __syncthreads();
    if (tid < M_DIM) red[tid] = red[tid] + red[M_DIM + tid];
    __syncthreads();
    if (tid < M_DIM) {
        float tot = 0.f;
        #pragma unroll
        for (int j = 0; j < M_DIM; j++) tot += red[j];
        out[item * M_DIM + tid] = logf(red[tid] / tot);
    }
}

extern "C" void kernel_launch(void* const* d_in, const int* in_sizes, int n_in,
                              void* d_out, int out_size) {
    const float* xfb = (const float*)d_in[0];
    const float* WT  = (const float*)d_in[1];
    int nx = in_sizes[0];
    // Defensive: ensure xfb is the big tensor
    if (n_in >= 2 && in_sizes[0] < in_sizes[1]) {
        xfb = (const float*)d_in[1];
        WT  = (const float*)d_in[0];
        nx  = in_sizes[1];
    }
    const int n_items = nx / (C_DIM * T_DIM);        // = 1024 (N*B)

    const size_t smem_bytes =
        (size_t)(2 * C_DIM * TT) * sizeof(float)     // x double buffer (90,112 B)
        + (size_t)(C_DIM * M_DIM) * sizeof(u64)      // dup'd W pairs   ( 2,816 B)
        + 32 * sizeof(float);                        // reduction scratch

    cudaFuncSetAttribute((const void*)csp_kernel,
                         cudaFuncAttributeMaxDynamicSharedMemorySize,
                         (int)smem_bytes);

    csp_kernel<<<n_items, BLOCK, smem_bytes>>>(xfb, WT, (float*)d_out);
}